// round 12
// baseline (speedup 1.0000x reference)
#include <cuda_runtime.h>
#include <math.h>
#include <stdint.h>

#define NTOK 8192
#define DIM 1024
#define TRIPLE 3072
#define TSEQ 2048
#define NB 4
#define NH 16
#define DH 64
#define ATT_SCALE 0.125f

// Scratch (allocation-free: device globals)
__device__ float g_xn[(size_t)NTOK * DIM];       // 32 MB (tf32-rounded)
__device__ float g_qkv[(size_t)NTOK * TRIPLE];   // 96 MB (tf32-rounded)
__device__ float g_ao[(size_t)NTOK * DIM];       // 32 MB (tf32-rounded)
__device__ float g_wqkv[(size_t)DIM * TRIPLE];   // 12 MB (tf32-rounded weights)
__device__ float g_wout[(size_t)DIM * DIM];      //  4 MB

// ---------------------------------------------------------------------------
// Helpers
// ---------------------------------------------------------------------------
__device__ __forceinline__ float f2tf32(float f) {
    uint32_t r;
    asm("cvt.rna.tf32.f32 %0, %1;" : "=r"(r) : "f"(f));
    return __uint_as_float(r);
}

__device__ __forceinline__ float4 cvt4(float4 v) {
    float4 o;
    o.x = f2tf32(v.x); o.y = f2tf32(v.y); o.z = f2tf32(v.z); o.w = f2tf32(v.w);
    return o;
}

__device__ __forceinline__ void mma_tf32(float c[4],
                                         uint32_t a0, uint32_t a1, uint32_t a2, uint32_t a3,
                                         uint32_t b0, uint32_t b1) {
    asm volatile(
        "mma.sync.aligned.m16n8k8.row.col.f32.tf32.tf32.f32 "
        "{%0,%1,%2,%3}, {%4,%5,%6,%7}, {%8,%9}, {%0,%1,%2,%3};"
        : "+f"(c[0]), "+f"(c[1]), "+f"(c[2]), "+f"(c[3])
        : "r"(a0), "r"(a1), "r"(a2), "r"(a3), "r"(b0), "r"(b1));
}

__device__ __forceinline__ void cp16(void* smem_dst, const void* gmem_src) {
    uint32_t s = (uint32_t)__cvta_generic_to_shared(smem_dst);
    asm volatile("cp.async.cg.shared.global [%0], [%1], 16;" :: "r"(s), "l"(gmem_src));
}
#define CP_COMMIT() asm volatile("cp.async.commit_group;" ::: "memory")
#define CP_WAIT0()  asm volatile("cp.async.wait_group 0;" ::: "memory")

// ---------------------------------------------------------------------------
// Weight rounding: fp32 -> tf32-rounded fp32 (grid-stride float4)
// ---------------------------------------------------------------------------
__global__ __launch_bounds__(256) void round_w_kernel(
    const float* __restrict__ in, float* __restrict__ out, int n4)
{
    int i = blockIdx.x * blockDim.x + threadIdx.x;
    if (i < n4) {
        float4 v = reinterpret_cast<const float4*>(in)[i];
        reinterpret_cast<float4*>(out)[i] = cvt4(v);
    }
}

// ---------------------------------------------------------------------------
// LayerNorm: one block per row of 1024, 256 threads x float4. Output tf32-rounded.
// ---------------------------------------------------------------------------
__global__ __launch_bounds__(256) void ln_kernel(
    const float* __restrict__ x,
    const float* __restrict__ gamma,
    const float* __restrict__ beta)
{
    int row = blockIdx.x;
    int t = threadIdx.x;
    const float4* xr = reinterpret_cast<const float4*>(x) + (size_t)row * (DIM / 4);
    float4 v = xr[t];

    __shared__ float red[8];

    float s = v.x + v.y + v.z + v.w;
    #pragma unroll
    for (int o = 16; o > 0; o >>= 1) s += __shfl_xor_sync(0xffffffffu, s, o);
    if ((t & 31) == 0) red[t >> 5] = s;
    __syncthreads();
    float mu = 0.f;
    #pragma unroll
    for (int i = 0; i < 8; i++) mu += red[i];
    mu *= (1.0f / DIM);
    __syncthreads();

    float dx = v.x - mu, dy = v.y - mu, dz = v.z - mu, dw = v.w - mu;
    float s2 = dx * dx + dy * dy + dz * dz + dw * dw;
    #pragma unroll
    for (int o = 16; o > 0; o >>= 1) s2 += __shfl_xor_sync(0xffffffffu, s2, o);
    if ((t & 31) == 0) red[t >> 5] = s2;
    __syncthreads();
    float var = 0.f;
    #pragma unroll
    for (int i = 0; i < 8; i++) var += red[i];
    var *= (1.0f / DIM);
    float r = rsqrtf(var + 1e-5f);

    float4 g = reinterpret_cast<const float4*>(gamma)[t];
    float4 bb = reinterpret_cast<const float4*>(beta)[t];
    float4 o;
    o.x = dx * r * g.x + bb.x;
    o.y = dy * r * g.y + bb.y;
    o.z = dz * r * g.z + bb.z;
    o.w = dw * r * g.w + bb.w;
    reinterpret_cast<float4*>(g_xn)[(size_t)row * (DIM / 4) + t] = cvt4(o);
}

// ---------------------------------------------------------------------------
// tf32 GEMM, cp.async double-buffered. C[M,N] = A[M,K] @ B[K,N] (+bias).
// CTA tile 128x128x32, 128 threads = 4 warps (2m x 2n), warp tile 64x64.
// Inner loop f-outer with just-in-time B fragments: live B regs 16 -> 2,
// targeting <=~240 regs so 2 CTAs/SM actually fit (R4 measured 254 -> 1 CTA).
// Dyn smem: As[2][128][36], Bs[2][32][136] = 71,680 B.
// ---------------------------------------------------------------------------
#define GS_AS (128 * 36)
#define GS_BS (32 * 136)
#define GEMM_SMEM_BYTES ((2 * GS_AS + 2 * GS_BS) * (int)sizeof(float))

template <bool HAS_BIAS, bool ROUND_OUT>
__global__ __launch_bounds__(128, 2) void gemm_tf32_pipe(
    const float* __restrict__ A,
    const float* __restrict__ Bm,
    float* __restrict__ C,
    int M, int N, int K,
    const float* __restrict__ bias)
{
    extern __shared__ __align__(16) float smg[];
    float* AsBase = smg;                 // [2][128][36]
    float* BsBase = smg + 2 * GS_AS;     // [2][32][136]

    int t = threadIdx.x;
    int lane = t & 31;
    int warp = t >> 5;       // 0..3
    int warp_m = warp & 1;   // m offset *64
    int warp_n = warp >> 1;  // n offset *64
    int grp = lane >> 2;     // 0..7
    int tg = lane & 3;       // 0..3
    int mBase = blockIdx.y * 128;
    int nBase = blockIdx.x * 128;

    float acc[4][8][4];
    #pragma unroll
    for (int mi = 0; mi < 4; mi++)
        #pragma unroll
        for (int f = 0; f < 8; f++)
            #pragma unroll
            for (int j = 0; j < 4; j++) acc[mi][f][j] = 0.f;

    // Prefetch tile 0
    {
        float* As = AsBase;
        float* Bs = BsBase;
        #pragma unroll
        for (int i = 0; i < 8; i++) {
            int fid = t + i * 128;
            int ar = fid >> 3, ak = (fid & 7) << 2;
            cp16(&As[ar * 36 + ak], &A[(size_t)(mBase + ar) * K + ak]);
        }
        #pragma unroll
        for (int i = 0; i < 8; i++) {
            int fid = t + i * 128;
            int br = fid >> 5, bc = (fid & 31) << 2;
            cp16(&Bs[br * 136 + bc], &Bm[(size_t)br * N + nBase + bc]);
        }
        CP_COMMIT();
    }

    int T = K / 32;
    for (int kt = 0; kt < T; kt++) {
        CP_WAIT0();
        __syncthreads();
        if (kt + 1 < T) {
            int k0 = (kt + 1) * 32;
            int sn = (kt + 1) & 1;
            float* As = AsBase + sn * GS_AS;
            float* Bs = BsBase + sn * GS_BS;
            #pragma unroll
            for (int i = 0; i < 8; i++) {
                int fid = t + i * 128;
                int ar = fid >> 3, ak = (fid & 7) << 2;
                cp16(&As[ar * 36 + ak], &A[(size_t)(mBase + ar) * K + k0 + ak]);
            }
            #pragma unroll
            for (int i = 0; i < 8; i++) {
                int fid = t + i * 128;
                int br = fid >> 5, bc = (fid & 31) << 2;
                cp16(&Bs[br * 136 + bc], &Bm[(size_t)(k0 + br) * N + nBase + bc]);
            }
            CP_COMMIT();
        }

        const float* As = AsBase + (kt & 1) * GS_AS;
        const float* Bs = BsBase + (kt & 1) * GS_BS;
        #pragma unroll
        for (int ks = 0; ks < 4; ks++) {
            int k = ks * 8;
            // A fragments cached for this k-step (16 regs)
            uint32_t af[4][4];
            #pragma unroll
            for (int mi = 0; mi < 4; mi++) {
                int m = warp_m * 64 + mi * 16;
                af[mi][0] = __float_as_uint(As[(m + grp) * 36 + k + tg]);
                af[mi][1] = __float_as_uint(As[(m + grp + 8) * 36 + k + tg]);
                af[mi][2] = __float_as_uint(As[(m + grp) * 36 + k + tg + 4]);
                af[mi][3] = __float_as_uint(As[(m + grp + 8) * 36 + k + tg + 4]);
            }
            // B fragments just-in-time per f: live B regs = 2 (was 16)
            #pragma unroll
            for (int f = 0; f < 8; f++) {
                int n = warp_n * 64 + f * 8 + grp;
                uint32_t b0 = __float_as_uint(Bs[(k + tg) * 136 + n]);
                uint32_t b1 = __float_as_uint(Bs[(k + tg + 4) * 136 + n]);
                #pragma unroll
                for (int mi = 0; mi < 4; mi++)
                    mma_tf32(acc[mi][f], af[mi][0], af[mi][1], af[mi][2], af[mi][3],
                             b0, b1);
            }
        }
        // No trailing barrier: stage (kt&1) is next written by copy kt+2, which
        // every thread issues only after passing the kt+1 top barrier.
    }

    // Epilogue
    #pragma unroll
    for (int mi = 0; mi < 4; mi++) {
        int r0 = mBase + warp_m * 64 + mi * 16 + grp;
        #pragma unroll
        for (int f = 0; f < 8; f++) {
            int col = nBase + warp_n * 64 + f * 8 + 2 * tg;
            float2 c01 = make_float2(acc[mi][f][0], acc[mi][f][1]);
            float2 c23 = make_float2(acc[mi][f][2], acc[mi][f][3]);
            if (HAS_BIAS) {
                float b0v = bias[col], b1v = bias[col + 1];
                c01.x += b0v; c01.y += b1v;
                c23.x += b0v; c23.y += b1v;
            }
            if (ROUND_OUT) {
                c01.x = f2tf32(c01.x); c01.y = f2tf32(c01.y);
                c23.x = f2tf32(c23.x); c23.y = f2tf32(c23.y);
            }
            *reinterpret_cast<float2*>(&C[(size_t)r0 * N + col]) = c01;
            *reinterpret_cast<float2*>(&C[(size_t)(r0 + 8) * N + col]) = c23;
        }
    }
}

// ---------------------------------------------------------------------------
// Flash attention with tf32 tensor cores, fp32 online softmax, cp.async K/V
// double buffering. Block = (128-query tile, head, batch); 8 warps x 16 q rows.
// qkv is pre-rounded tf32; Q scale 0.125 is exact so no re-rounding needed.
// Dyn smem floats: Ks[2][64][68], Vs[2][64][72], QPs[128][68] = 106,496 B.
// ---------------------------------------------------------------------------
#define KS_STRIDE 68
#define VS_STRIDE 72
#define QP_STRIDE 68
#define AT_KS (64 * KS_STRIDE)
#define AT_VS (64 * VS_STRIDE)
#define ATT_SMEM_FLOATS (2 * AT_KS + 2 * AT_VS + 128 * QP_STRIDE)

__global__ __launch_bounds__(256, 2) void attn_tc_kernel(
    const float* __restrict__ qkv,
    float* __restrict__ ao)
{
    extern __shared__ __align__(16) float sm[];
    float* KsBase = sm;                       // [2][64][68]
    float* VsBase = sm + 2 * AT_KS;           // [2][64][72]
    float* QPs    = sm + 2 * AT_KS + 2 * AT_VS; // [128][68]

    int t = threadIdx.x;
    int lane = t & 31;
    int warp = t >> 5;     // 0..7
    int grp = lane >> 2;   // 0..7
    int tg = lane & 3;     // 0..3
    int wq = warp * 16;

    int qtile = blockIdx.x;
    int h = blockIdx.y;
    int b = blockIdx.z;

    size_t tokRowBase = (size_t)b * TSEQ;
    const float* Qg = qkv + tokRowBase * TRIPLE + h * DH;
    const float* Kg = qkv + tokRowBase * TRIPLE + DIM + h * DH;
    const float* Vg = qkv + tokRowBase * TRIPLE + 2 * DIM + h * DH;
    int qBase = qtile * 128;

    // Prefetch K/V tile 0 into stage 0
    {
        float* Ks = KsBase;
        float* Vs = VsBase;
        #pragma unroll
        for (int i = 0; i < 4; i++) {
            int fid = t + i * 256;
            int r = fid >> 4, c = (fid & 15) << 2;
            cp16(&Ks[r * KS_STRIDE + c], &Kg[(size_t)r * TRIPLE + c]);
            cp16(&Vs[r * VS_STRIDE + c], &Vg[(size_t)r * TRIPLE + c]);
        }
        CP_COMMIT();
    }

    // Stage this warp's 16 Q rows (scaled; qkv pre-rounded, x0.125 exact)
    #pragma unroll
    for (int i = 0; i < 8; i++) {
        int fid = i * 32 + lane;
        int r = fid >> 4;
        int c = (fid & 15) << 2;
        float4 v = *reinterpret_cast<const float4*>(
            &Qg[(size_t)(qBase + wq + r) * TRIPLE + c]);
        v.x *= ATT_SCALE; v.y *= ATT_SCALE; v.z *= ATT_SCALE; v.w *= ATT_SCALE;
        *reinterpret_cast<float4*>(&QPs[(wq + r) * QP_STRIDE + c]) = v;
    }
    __syncwarp();

    uint32_t qa[8][4];
    #pragma unroll
    for (int ks = 0; ks < 8; ks++) {
        int k = ks * 8;
        qa[ks][0] = __float_as_uint(QPs[(wq + grp) * QP_STRIDE + k + tg]);
        qa[ks][1] = __float_as_uint(QPs[(wq + grp + 8) * QP_STRIDE + k + tg]);
        qa[ks][2] = __float_as_uint(QPs[(wq + grp) * QP_STRIDE + k + tg + 4]);
        qa[ks][3] = __float_as_uint(QPs[(wq + grp + 8) * QP_STRIDE + k + tg + 4]);
    }

    float o_acc[8][4];
    #pragma unroll
    for (int f = 0; f < 8; f++)
        #pragma unroll
        for (int j = 0; j < 4; j++) o_acc[f][j] = 0.f;
    float m0 = -INFINITY, m1 = -INFINITY, l0 = 0.f, l1 = 0.f;

    const int NT = TSEQ / 64;
    for (int kt = 0; kt < NT; kt++) {
        CP_WAIT0();
        __syncthreads();
        if (kt + 1 < NT) {
            int kBase = (kt + 1) * 64;
            int sn = (kt + 1) & 1;
            float* Ks = KsBase + sn * AT_KS;
            float* Vs = VsBase + sn * AT_VS;
            #pragma unroll
            for (int i = 0; i < 4; i++) {
                int fid = t + i * 256;
                int r = fid >> 4, c = (fid & 15) << 2;
                cp16(&Ks[r * KS_STRIDE + c], &Kg[(size_t)(kBase + r) * TRIPLE + c]);
                cp16(&Vs[r * VS_STRIDE + c], &Vg[(size_t)(kBase + r) * TRIPLE + c]);
            }
            CP_COMMIT();
        }
        const float* Ks = KsBase + (kt & 1) * AT_KS;
        const float* Vs = VsBase + (kt & 1) * AT_VS;

        // S = Q K^T : warp computes 16 x 64
        float s[8][4];
        #pragma unroll
        for (int f = 0; f < 8; f++)
            #pragma unroll
            for (int j = 0; j < 4; j++) s[f][j] = 0.f;
        #pragma unroll
        for (int ks = 0; ks < 8; ks++) {
            int k = ks * 8;
            #pragma unroll
            for (int f = 0; f < 8; f++) {
                int key = f * 8 + grp;
                uint32_t b0 = __float_as_uint(Ks[key * KS_STRIDE + k + tg]);
                uint32_t b1 = __float_as_uint(Ks[key * KS_STRIDE + k + tg + 4]);
                mma_tf32(s[f], qa[ks][0], qa[ks][1], qa[ks][2], qa[ks][3], b0, b1);
            }
        }

        // Online softmax for the thread's two rows
        float rm0 = -INFINITY, rm1 = -INFINITY;
        #pragma unroll
        for (int f = 0; f < 8; f++) {
            rm0 = fmaxf(rm0, fmaxf(s[f][0], s[f][1]));
            rm1 = fmaxf(rm1, fmaxf(s[f][2], s[f][3]));
        }
        #pragma unroll
        for (int o = 1; o <= 2; o <<= 1) {
            rm0 = fmaxf(rm0, __shfl_xor_sync(0xffffffffu, rm0, o));
            rm1 = fmaxf(rm1, __shfl_xor_sync(0xffffffffu, rm1, o));
        }
        float mn0 = fmaxf(m0, rm0), mn1 = fmaxf(m1, rm1);
        float a0 = __expf(m0 - mn0), a1 = __expf(m1 - mn1);
        float rs0 = 0.f, rs1 = 0.f;
        #pragma unroll
        for (int f = 0; f < 8; f++) {
            s[f][0] = __expf(s[f][0] - mn0);
            s[f][1] = __expf(s[f][1] - mn0);
            s[f][2] = __expf(s[f][2] - mn1);
            s[f][3] = __expf(s[f][3] - mn1);
            rs0 += s[f][0] + s[f][1];
            rs1 += s[f][2] + s[f][3];
        }
        #pragma unroll
        for (int o = 1; o <= 2; o <<= 1) {
            rs0 += __shfl_xor_sync(0xffffffffu, rs0, o);
            rs1 += __shfl_xor_sync(0xffffffffu, rs1, o);
        }
        l0 = l0 * a0 + rs0;
        l1 = l1 * a1 + rs1;
        m0 = mn0; m1 = mn1;
        #pragma unroll
        for (int f = 0; f < 8; f++) {
            o_acc[f][0] *= a0; o_acc[f][1] *= a0;
            o_acc[f][2] *= a1; o_acc[f][3] *= a1;
        }

        // Write P (tf32) into this warp's own QPs rows: [q][key]
        #pragma unroll
        for (int f = 0; f < 8; f++) {
            int col = f * 8 + 2 * tg;
            float2 p01 = make_float2(f2tf32(s[f][0]), f2tf32(s[f][1]));
            float2 p23 = make_float2(f2tf32(s[f][2]), f2tf32(s[f][3]));
            *reinterpret_cast<float2*>(&QPs[(wq + grp) * QP_STRIDE + col]) = p01;
            *reinterpret_cast<float2*>(&QPs[(wq + grp + 8) * QP_STRIDE + col]) = p23;
        }
        __syncwarp();

        // O += P @ V
        #pragma unroll
        for (int ks = 0; ks < 8; ks++) {
            int k = ks * 8;
            uint32_t pa0 = __float_as_uint(QPs[(wq + grp) * QP_STRIDE + k + tg]);
            uint32_t pa1 = __float_as_uint(QPs[(wq + grp + 8) * QP_STRIDE + k + tg]);
            uint32_t pa2 = __float_as_uint(QPs[(wq + grp) * QP_STRIDE + k + tg + 4]);
            uint32_t pa3 = __float_as_uint(QPs[(wq + grp + 8) * QP_STRIDE + k + tg + 4]);
            #pragma unroll
            for (int f = 0; f < 8; f++) {
                int n = f * 8 + grp;
                uint32_t b0 = __float_as_uint(Vs[(k + tg) * VS_STRIDE + n]);
                uint32_t b1 = __float_as_uint(Vs[(k + tg + 4) * VS_STRIDE + n]);
                mma_tf32(o_acc[f], pa0, pa1, pa2, pa3, b0, b1);
            }
        }
        // No trailing barrier: stage (kt&1) next written by copy kt+2 issued
        // after the kt+1 top barrier.
    }

    // Normalize + write out (tf32-rounded for the out-projection consumer)
    float inv0 = 1.0f / l0, inv1 = 1.0f / l1;
    size_t gr0 = tokRowBase + qBase + wq + grp;
    size_t gr1 = gr0 + 8;
    #pragma unroll
    for (int f = 0; f < 8; f++) {
        int col = h * DH + f * 8 + 2 * tg;
        float2 c01 = make_float2(f2tf32(o_acc[f][0] * inv0), f2tf32(o_acc[f][1] * inv0));
        float2 c23 = make_float2(f2tf32(o_acc[f][2] * inv1), f2tf32(o_acc[f][3] * inv1));
        *reinterpret_cast<float2*>(&ao[gr0 * DIM + col]) = c01;
        *reinterpret_cast<float2*>(&ao[gr1 * DIM + col]) = c23;
    }
}

// ---------------------------------------------------------------------------
extern "C" void kernel_launch(void* const* d_in, const int* in_sizes, int n_in,
                              void* d_out, int out_size)
{
    const float* x      = (const float*)d_in[0];
    const float* gamma  = (const float*)d_in[1];
    const float* beta   = (const float*)d_in[2];
    const float* w_qkv  = (const float*)d_in[3];
    const float* w_out  = (const float*)d_in[4];
    const float* b_out  = (const float*)d_in[5];
    float* out = (float*)d_out;

    void* p;
    cudaGetSymbolAddress(&p, g_xn);   float* xn    = (float*)p;
    cudaGetSymbolAddress(&p, g_qkv);  float* qkv   = (float*)p;
    cudaGetSymbolAddress(&p, g_ao);   float* ao    = (float*)p;
    cudaGetSymbolAddress(&p, g_wqkv); float* wqkvt = (float*)p;
    cudaGetSymbolAddress(&p, g_wout); float* woutt = (float*)p;

    // 0) Round weights to tf32 once per launch (cheap, memory-bound)
    round_w_kernel<<<(DIM * TRIPLE / 4 + 255) / 256, 256>>>(w_qkv, wqkvt, DIM * TRIPLE / 4);
    round_w_kernel<<<(DIM * DIM / 4 + 255) / 256, 256>>>(w_out, woutt, DIM * DIM / 4);

    // 1) LayerNorm (writes tf32-rounded xn)
    ln_kernel<<<NTOK, 256>>>(x, gamma, beta);

    // 2) QKV projection: [8192,1024] @ [1024,3072] -> tf32-rounded qkv
    cudaFuncSetAttribute(gemm_tf32_pipe<false, true>,
                         cudaFuncAttributeMaxDynamicSharedMemorySize, GEMM_SMEM_BYTES);
    gemm_tf32_pipe<false, true><<<dim3(TRIPLE / 128, NTOK / 128), 128, GEMM_SMEM_BYTES>>>(
        xn, wqkvt, qkv, NTOK, TRIPLE, DIM, nullptr);

    // 3) Attention (tensor-core, cp.async pipelined)
    int att_smem = ATT_SMEM_FLOATS * (int)sizeof(float); // 106,496 B
    cudaFuncSetAttribute(attn_tc_kernel,
                         cudaFuncAttributeMaxDynamicSharedMemorySize, att_smem);
    attn_tc_kernel<<<dim3(TSEQ / 128, NH, NB), 256, att_smem>>>(qkv, ao);

    // 4) Output projection + bias: [8192,1024] @ [1024,1024] + b
    cudaFuncSetAttribute(gemm_tf32_pipe<true, false>,
                         cudaFuncAttributeMaxDynamicSharedMemorySize, GEMM_SMEM_BYTES);
    gemm_tf32_pipe<true, false><<<dim3(DIM / 128, NTOK / 128), 128, GEMM_SMEM_BYTES>>>(
        ao, woutt, out, NTOK, DIM, DIM, b_out);
}

// round 14
// speedup vs baseline: 1.0010x; 1.0010x over previous
#include <cuda_runtime.h>
#include <math.h>
#include <stdint.h>

#define NTOK 8192
#define DIM 1024
#define TRIPLE 3072
#define TSEQ 2048
#define NB 4
#define NH 16
#define DH 64
#define ATT_SCALE 0.125f

// Scratch (allocation-free: device globals)
__device__ float g_xn[(size_t)NTOK * DIM];       // 32 MB (tf32-rounded)
__device__ float g_qkv[(size_t)NTOK * TRIPLE];   // 96 MB (tf32-rounded)
__device__ float g_ao[(size_t)NTOK * DIM];       // 32 MB (tf32-rounded)
__device__ float g_wqkv[(size_t)DIM * TRIPLE];   // 12 MB (tf32-rounded weights)
__device__ float g_wout[(size_t)DIM * DIM];      //  4 MB

// ---------------------------------------------------------------------------
// Helpers
// ---------------------------------------------------------------------------
__device__ __forceinline__ float f2tf32(float f) {
    uint32_t r;
    asm("cvt.rna.tf32.f32 %0, %1;" : "=r"(r) : "f"(f));
    return __uint_as_float(r);
}

__device__ __forceinline__ float4 cvt4(float4 v) {
    float4 o;
    o.x = f2tf32(v.x); o.y = f2tf32(v.y); o.z = f2tf32(v.z); o.w = f2tf32(v.w);
    return o;
}

__device__ __forceinline__ void mma_tf32(float c[4],
                                         uint32_t a0, uint32_t a1, uint32_t a2, uint32_t a3,
                                         uint32_t b0, uint32_t b1) {
    asm volatile(
        "mma.sync.aligned.m16n8k8.row.col.f32.tf32.tf32.f32 "
        "{%0,%1,%2,%3}, {%4,%5,%6,%7}, {%8,%9}, {%0,%1,%2,%3};"
        : "+f"(c[0]), "+f"(c[1]), "+f"(c[2]), "+f"(c[3])
        : "r"(a0), "r"(a1), "r"(a2), "r"(a3), "r"(b0), "r"(b1));
}

__device__ __forceinline__ void cp16(void* smem_dst, const void* gmem_src) {
    uint32_t s = (uint32_t)__cvta_generic_to_shared(smem_dst);
    asm volatile("cp.async.cg.shared.global [%0], [%1], 16;" :: "r"(s), "l"(gmem_src));
}
#define CP_COMMIT() asm volatile("cp.async.commit_group;" ::: "memory")
#define CP_WAIT0()  asm volatile("cp.async.wait_group 0;" ::: "memory")

// ---------------------------------------------------------------------------
// Weight rounding: fp32 -> tf32-rounded fp32 (grid-stride float4)
// ---------------------------------------------------------------------------
__global__ __launch_bounds__(256) void round_w_kernel(
    const float* __restrict__ in, float* __restrict__ out, int n4)
{
    int i = blockIdx.x * blockDim.x + threadIdx.x;
    if (i < n4) {
        float4 v = reinterpret_cast<const float4*>(in)[i];
        reinterpret_cast<float4*>(out)[i] = cvt4(v);
    }
}

// ---------------------------------------------------------------------------
// LayerNorm: one block per row of 1024, 256 threads x float4. Output tf32-rounded.
// ---------------------------------------------------------------------------
__global__ __launch_bounds__(256) void ln_kernel(
    const float* __restrict__ x,
    const float* __restrict__ gamma,
    const float* __restrict__ beta)
{
    int row = blockIdx.x;
    int t = threadIdx.x;
    const float4* xr = reinterpret_cast<const float4*>(x) + (size_t)row * (DIM / 4);
    float4 v = xr[t];

    __shared__ float red[8];

    float s = v.x + v.y + v.z + v.w;
    #pragma unroll
    for (int o = 16; o > 0; o >>= 1) s += __shfl_xor_sync(0xffffffffu, s, o);
    if ((t & 31) == 0) red[t >> 5] = s;
    __syncthreads();
    float mu = 0.f;
    #pragma unroll
    for (int i = 0; i < 8; i++) mu += red[i];
    mu *= (1.0f / DIM);
    __syncthreads();

    float dx = v.x - mu, dy = v.y - mu, dz = v.z - mu, dw = v.w - mu;
    float s2 = dx * dx + dy * dy + dz * dz + dw * dw;
    #pragma unroll
    for (int o = 16; o > 0; o >>= 1) s2 += __shfl_xor_sync(0xffffffffu, s2, o);
    if ((t & 31) == 0) red[t >> 5] = s2;
    __syncthreads();
    float var = 0.f;
    #pragma unroll
    for (int i = 0; i < 8; i++) var += red[i];
    var *= (1.0f / DIM);
    float r = rsqrtf(var + 1e-5f);

    float4 g = reinterpret_cast<const float4*>(gamma)[t];
    float4 bb = reinterpret_cast<const float4*>(beta)[t];
    float4 o;
    o.x = dx * r * g.x + bb.x;
    o.y = dy * r * g.y + bb.y;
    o.z = dz * r * g.z + bb.z;
    o.w = dw * r * g.w + bb.w;
    reinterpret_cast<float4*>(g_xn)[(size_t)row * (DIM / 4) + t] = cvt4(o);
}

// ---------------------------------------------------------------------------
// tf32 GEMM, cp.async double-buffered. C[M,N] = A[M,K] @ B[K,N] (+bias).
// CTA tile 128x128x32, 256 threads = 8 warps (4m x 2n), warp tile 32x64.
// acc = 64 regs/thread -> ~110-125 regs total, so 2 CTAs/SM = 16 warps
// = 4 warps/SMSP (R12 showed 64x64 warp tile pins regs at 254 -> only
// 2 warps/SMSP, tensor stuck at 54% on LDS->HMMA dependency bubbles).
// Dyn smem: As[2][128][36], Bs[2][32][136] = 71,680 B (x2 CTA = 143 KB OK).
// ---------------------------------------------------------------------------
#define GS_AS (128 * 36)
#define GS_BS (32 * 136)
#define GEMM_SMEM_BYTES ((2 * GS_AS + 2 * GS_BS) * (int)sizeof(float))

template <bool HAS_BIAS, bool ROUND_OUT>
__global__ __launch_bounds__(256, 2) void gemm_tf32_pipe(
    const float* __restrict__ A,
    const float* __restrict__ Bm,
    float* __restrict__ C,
    int M, int N, int K,
    const float* __restrict__ bias)
{
    extern __shared__ __align__(16) float smg[];
    float* AsBase = smg;                 // [2][128][36]
    float* BsBase = smg + 2 * GS_AS;     // [2][32][136]

    int t = threadIdx.x;
    int lane = t & 31;
    int warp = t >> 5;       // 0..7
    int warp_m = warp & 3;   // m offset *32
    int warp_n = warp >> 2;  // n offset *64
    int grp = lane >> 2;     // 0..7
    int tg = lane & 3;       // 0..3
    int mBase = blockIdx.y * 128;
    int nBase = blockIdx.x * 128;

    float acc[2][8][4];
    #pragma unroll
    for (int mi = 0; mi < 2; mi++)
        #pragma unroll
        for (int f = 0; f < 8; f++)
            #pragma unroll
            for (int j = 0; j < 4; j++) acc[mi][f][j] = 0.f;

    // Prefetch tile 0 (1024 float4 per tensor tile, 256 threads -> 4 each)
    {
        float* As = AsBase;
        float* Bs = BsBase;
        #pragma unroll
        for (int i = 0; i < 4; i++) {
            int fid = t + i * 256;
            int ar = fid >> 3, ak = (fid & 7) << 2;
            cp16(&As[ar * 36 + ak], &A[(size_t)(mBase + ar) * K + ak]);
        }
        #pragma unroll
        for (int i = 0; i < 4; i++) {
            int fid = t + i * 256;
            int br = fid >> 5, bc = (fid & 31) << 2;
            cp16(&Bs[br * 136 + bc], &Bm[(size_t)br * N + nBase + bc]);
        }
        CP_COMMIT();
    }

    int T = K / 32;
    for (int kt = 0; kt < T; kt++) {
        CP_WAIT0();
        __syncthreads();
        if (kt + 1 < T) {
            int k0 = (kt + 1) * 32;
            int sn = (kt + 1) & 1;
            float* As = AsBase + sn * GS_AS;
            float* Bs = BsBase + sn * GS_BS;
            #pragma unroll
            for (int i = 0; i < 4; i++) {
                int fid = t + i * 256;
                int ar = fid >> 3, ak = (fid & 7) << 2;
                cp16(&As[ar * 36 + ak], &A[(size_t)(mBase + ar) * K + k0 + ak]);
            }
            #pragma unroll
            for (int i = 0; i < 4; i++) {
                int fid = t + i * 256;
                int br = fid >> 5, bc = (fid & 31) << 2;
                cp16(&Bs[br * 136 + bc], &Bm[(size_t)(k0 + br) * N + nBase + bc]);
            }
            CP_COMMIT();
        }

        const float* As = AsBase + (kt & 1) * GS_AS;
        const float* Bs = BsBase + (kt & 1) * GS_BS;
        #pragma unroll
        for (int ks = 0; ks < 4; ks++) {
            int k = ks * 8;
            // A fragments for this k-step: 2 mi x 4 = 8 regs
            uint32_t af[2][4];
            #pragma unroll
            for (int mi = 0; mi < 2; mi++) {
                int m = warp_m * 32 + mi * 16;
                af[mi][0] = __float_as_uint(As[(m + grp) * 36 + k + tg]);
                af[mi][1] = __float_as_uint(As[(m + grp + 8) * 36 + k + tg]);
                af[mi][2] = __float_as_uint(As[(m + grp) * 36 + k + tg + 4]);
                af[mi][3] = __float_as_uint(As[(m + grp + 8) * 36 + k + tg + 4]);
            }
            #pragma unroll
            for (int f = 0; f < 8; f++) {
                int n = warp_n * 64 + f * 8 + grp;
                uint32_t b0 = __float_as_uint(Bs[(k + tg) * 136 + n]);
                uint32_t b1 = __float_as_uint(Bs[(k + tg + 4) * 136 + n]);
                #pragma unroll
                for (int mi = 0; mi < 2; mi++)
                    mma_tf32(acc[mi][f], af[mi][0], af[mi][1], af[mi][2], af[mi][3],
                             b0, b1);
            }
        }
        // No trailing barrier: stage (kt&1) is next written by copy kt+2, which
        // every thread issues only after passing the kt+1 top barrier.
    }

    // Epilogue
    #pragma unroll
    for (int mi = 0; mi < 2; mi++) {
        int r0 = mBase + warp_m * 32 + mi * 16 + grp;
        #pragma unroll
        for (int f = 0; f < 8; f++) {
            int col = nBase + warp_n * 64 + f * 8 + 2 * tg;
            float2 c01 = make_float2(acc[mi][f][0], acc[mi][f][1]);
            float2 c23 = make_float2(acc[mi][f][2], acc[mi][f][3]);
            if (HAS_BIAS) {
                float b0v = bias[col], b1v = bias[col + 1];
                c01.x += b0v; c01.y += b1v;
                c23.x += b0v; c23.y += b1v;
            }
            if (ROUND_OUT) {
                c01.x = f2tf32(c01.x); c01.y = f2tf32(c01.y);
                c23.x = f2tf32(c23.x); c23.y = f2tf32(c23.y);
            }
            *reinterpret_cast<float2*>(&C[(size_t)r0 * N + col]) = c01;
            *reinterpret_cast<float2*>(&C[(size_t)(r0 + 8) * N + col]) = c23;
        }
    }
}

// ---------------------------------------------------------------------------
// Flash attention with tf32 tensor cores, fp32 online softmax, cp.async K/V
// double buffering. Block = (128-query tile, head, batch); 8 warps x 16 q rows.
// qkv is pre-rounded tf32; Q scale 0.125 is exact so no re-rounding needed.
// Dyn smem floats: Ks[2][64][68], Vs[2][64][72], QPs[128][68] = 106,496 B.
// ---------------------------------------------------------------------------
#define KS_STRIDE 68
#define VS_STRIDE 72
#define QP_STRIDE 68
#define AT_KS (64 * KS_STRIDE)
#define AT_VS (64 * VS_STRIDE)
#define ATT_SMEM_FLOATS (2 * AT_KS + 2 * AT_VS + 128 * QP_STRIDE)

__global__ __launch_bounds__(256, 2) void attn_tc_kernel(
    const float* __restrict__ qkv,
    float* __restrict__ ao)
{
    extern __shared__ __align__(16) float sm[];
    float* KsBase = sm;                       // [2][64][68]
    float* VsBase = sm + 2 * AT_KS;           // [2][64][72]
    float* QPs    = sm + 2 * AT_KS + 2 * AT_VS; // [128][68]

    int t = threadIdx.x;
    int lane = t & 31;
    int warp = t >> 5;     // 0..7
    int grp = lane >> 2;   // 0..7
    int tg = lane & 3;     // 0..3
    int wq = warp * 16;

    int qtile = blockIdx.x;
    int h = blockIdx.y;
    int b = blockIdx.z;

    size_t tokRowBase = (size_t)b * TSEQ;
    const float* Qg = qkv + tokRowBase * TRIPLE + h * DH;
    const float* Kg = qkv + tokRowBase * TRIPLE + DIM + h * DH;
    const float* Vg = qkv + tokRowBase * TRIPLE + 2 * DIM + h * DH;
    int qBase = qtile * 128;

    // Prefetch K/V tile 0 into stage 0
    {
        float* Ks = KsBase;
        float* Vs = VsBase;
        #pragma unroll
        for (int i = 0; i < 4; i++) {
            int fid = t + i * 256;
            int r = fid >> 4, c = (fid & 15) << 2;
            cp16(&Ks[r * KS_STRIDE + c], &Kg[(size_t)r * TRIPLE + c]);
            cp16(&Vs[r * VS_STRIDE + c], &Vg[(size_t)r * TRIPLE + c]);
        }
        CP_COMMIT();
    }

    // Stage this warp's 16 Q rows (scaled; qkv pre-rounded, x0.125 exact)
    #pragma unroll
    for (int i = 0; i < 8; i++) {
        int fid = i * 32 + lane;
        int r = fid >> 4;
        int c = (fid & 15) << 2;
        float4 v = *reinterpret_cast<const float4*>(
            &Qg[(size_t)(qBase + wq + r) * TRIPLE + c]);
        v.x *= ATT_SCALE; v.y *= ATT_SCALE; v.z *= ATT_SCALE; v.w *= ATT_SCALE;
        *reinterpret_cast<float4*>(&QPs[(wq + r) * QP_STRIDE + c]) = v;
    }
    __syncwarp();

    uint32_t qa[8][4];
    #pragma unroll
    for (int ks = 0; ks < 8; ks++) {
        int k = ks * 8;
        qa[ks][0] = __float_as_uint(QPs[(wq + grp) * QP_STRIDE + k + tg]);
        qa[ks][1] = __float_as_uint(QPs[(wq + grp + 8) * QP_STRIDE + k + tg]);
        qa[ks][2] = __float_as_uint(QPs[(wq + grp) * QP_STRIDE + k + tg + 4]);
        qa[ks][3] = __float_as_uint(QPs[(wq + grp + 8) * QP_STRIDE + k + tg + 4]);
    }

    float o_acc[8][4];
    #pragma unroll
    for (int f = 0; f < 8; f++)
        #pragma unroll
        for (int j = 0; j < 4; j++) o_acc[f][j] = 0.f;
    float m0 = -INFINITY, m1 = -INFINITY, l0 = 0.f, l1 = 0.f;

    const int NT = TSEQ / 64;
    for (int kt = 0; kt < NT; kt++) {
        CP_WAIT0();
        __syncthreads();
        if (kt + 1 < NT) {
            int kBase = (kt + 1) * 64;
            int sn = (kt + 1) & 1;
            float* Ks = KsBase + sn * AT_KS;
            float* Vs = VsBase + sn * AT_VS;
            #pragma unroll
            for (int i = 0; i < 4; i++) {
                int fid = t + i * 256;
                int r = fid >> 4, c = (fid & 15) << 2;
                cp16(&Ks[r * KS_STRIDE + c], &Kg[(size_t)(kBase + r) * TRIPLE + c]);
                cp16(&Vs[r * VS_STRIDE + c], &Vg[(size_t)(kBase + r) * TRIPLE + c]);
            }
            CP_COMMIT();
        }
        const float* Ks = KsBase + (kt & 1) * AT_KS;
        const float* Vs = VsBase + (kt & 1) * AT_VS;

        // S = Q K^T : warp computes 16 x 64
        float s[8][4];
        #pragma unroll
        for (int f = 0; f < 8; f++)
            #pragma unroll
            for (int j = 0; j < 4; j++) s[f][j] = 0.f;
        #pragma unroll
        for (int ks = 0; ks < 8; ks++) {
            int k = ks * 8;
            #pragma unroll
            for (int f = 0; f < 8; f++) {
                int key = f * 8 + grp;
                uint32_t b0 = __float_as_uint(Ks[key * KS_STRIDE + k + tg]);
                uint32_t b1 = __float_as_uint(Ks[key * KS_STRIDE + k + tg + 4]);
                mma_tf32(s[f], qa[ks][0], qa[ks][1], qa[ks][2], qa[ks][3], b0, b1);
            }
        }

        // Online softmax for the thread's two rows
        float rm0 = -INFINITY, rm1 = -INFINITY;
        #pragma unroll
        for (int f = 0; f < 8; f++) {
            rm0 = fmaxf(rm0, fmaxf(s[f][0], s[f][1]));
            rm1 = fmaxf(rm1, fmaxf(s[f][2], s[f][3]));
        }
        #pragma unroll
        for (int o = 1; o <= 2; o <<= 1) {
            rm0 = fmaxf(rm0, __shfl_xor_sync(0xffffffffu, rm0, o));
            rm1 = fmaxf(rm1, __shfl_xor_sync(0xffffffffu, rm1, o));
        }
        float mn0 = fmaxf(m0, rm0), mn1 = fmaxf(m1, rm1);
        float a0 = __expf(m0 - mn0), a1 = __expf(m1 - mn1);
        float rs0 = 0.f, rs1 = 0.f;
        #pragma unroll
        for (int f = 0; f < 8; f++) {
            s[f][0] = __expf(s[f][0] - mn0);
            s[f][1] = __expf(s[f][1] - mn0);
            s[f][2] = __expf(s[f][2] - mn1);
            s[f][3] = __expf(s[f][3] - mn1);
            rs0 += s[f][0] + s[f][1];
            rs1 += s[f][2] + s[f][3];
        }
        #pragma unroll
        for (int o = 1; o <= 2; o <<= 1) {
            rs0 += __shfl_xor_sync(0xffffffffu, rs0, o);
            rs1 += __shfl_xor_sync(0xffffffffu, rs1, o);
        }
        l0 = l0 * a0 + rs0;
        l1 = l1 * a1 + rs1;
        m0 = mn0; m1 = mn1;
        #pragma unroll
        for (int f = 0; f < 8; f++) {
            o_acc[f][0] *= a0; o_acc[f][1] *= a0;
            o_acc[f][2] *= a1; o_acc[f][3] *= a1;
        }

        // Write P (tf32) into this warp's own QPs rows: [q][key]
        #pragma unroll
        for (int f = 0; f < 8; f++) {
            int col = f * 8 + 2 * tg;
            float2 p01 = make_float2(f2tf32(s[f][0]), f2tf32(s[f][1]));
            float2 p23 = make_float2(f2tf32(s[f][2]), f2tf32(s[f][3]));
            *reinterpret_cast<float2*>(&QPs[(wq + grp) * QP_STRIDE + col]) = p01;
            *reinterpret_cast<float2*>(&QPs[(wq + grp + 8) * QP_STRIDE + col]) = p23;
        }
        __syncwarp();

        // O += P @ V
        #pragma unroll
        for (int ks = 0; ks < 8; ks++) {
            int k = ks * 8;
            uint32_t pa0 = __float_as_uint(QPs[(wq + grp) * QP_STRIDE + k + tg]);
            uint32_t pa1 = __float_as_uint(QPs[(wq + grp + 8) * QP_STRIDE + k + tg]);
            uint32_t pa2 = __float_as_uint(QPs[(wq + grp) * QP_STRIDE + k + tg + 4]);
            uint32_t pa3 = __float_as_uint(QPs[(wq + grp + 8) * QP_STRIDE + k + tg + 4]);
            #pragma unroll
            for (int f = 0; f < 8; f++) {
                int n = f * 8 + grp;
                uint32_t b0 = __float_as_uint(Vs[(k + tg) * VS_STRIDE + n]);
                uint32_t b1 = __float_as_uint(Vs[(k + tg + 4) * VS_STRIDE + n]);
                mma_tf32(o_acc[f], pa0, pa1, pa2, pa3, b0, b1);
            }
        }
        // No trailing barrier: stage (kt&1) next written by copy kt+2 issued
        // after the kt+1 top barrier.
    }

    // Normalize + write out (tf32-rounded for the out-projection consumer)
    float inv0 = 1.0f / l0, inv1 = 1.0f / l1;
    size_t gr0 = tokRowBase + qBase + wq + grp;
    size_t gr1 = gr0 + 8;
    #pragma unroll
    for (int f = 0; f < 8; f++) {
        int col = h * DH + f * 8 + 2 * tg;
        float2 c01 = make_float2(f2tf32(o_acc[f][0] * inv0), f2tf32(o_acc[f][1] * inv0));
        float2 c23 = make_float2(f2tf32(o_acc[f][2] * inv1), f2tf32(o_acc[f][3] * inv1));
        *reinterpret_cast<float2*>(&ao[gr0 * DIM + col]) = c01;
        *reinterpret_cast<float2*>(&ao[gr1 * DIM + col]) = c23;
    }
}

// ---------------------------------------------------------------------------
extern "C" void kernel_launch(void* const* d_in, const int* in_sizes, int n_in,
                              void* d_out, int out_size)
{
    const float* x      = (const float*)d_in[0];
    const float* gamma  = (const float*)d_in[1];
    const float* beta   = (const float*)d_in[2];
    const float* w_qkv  = (const float*)d_in[3];
    const float* w_out  = (const float*)d_in[4];
    const float* b_out  = (const float*)d_in[5];
    float* out = (float*)d_out;

    void* p;
    cudaGetSymbolAddress(&p, g_xn);   float* xn    = (float*)p;
    cudaGetSymbolAddress(&p, g_qkv);  float* qkv   = (float*)p;
    cudaGetSymbolAddress(&p, g_ao);   float* ao    = (float*)p;
    cudaGetSymbolAddress(&p, g_wqkv); float* wqkvt = (float*)p;
    cudaGetSymbolAddress(&p, g_wout); float* woutt = (float*)p;

    // 0) Round weights to tf32 once per launch (cheap, memory-bound)
    round_w_kernel<<<(DIM * TRIPLE / 4 + 255) / 256, 256>>>(w_qkv, wqkvt, DIM * TRIPLE / 4);
    round_w_kernel<<<(DIM * DIM / 4 + 255) / 256, 256>>>(w_out, woutt, DIM * DIM / 4);

    // 1) LayerNorm (writes tf32-rounded xn)
    ln_kernel<<<NTOK, 256>>>(x, gamma, beta);

    // 2) QKV projection: [8192,1024] @ [1024,3072] -> tf32-rounded qkv
    cudaFuncSetAttribute(gemm_tf32_pipe<false, true>,
                         cudaFuncAttributeMaxDynamicSharedMemorySize, GEMM_SMEM_BYTES);
    gemm_tf32_pipe<false, true><<<dim3(TRIPLE / 128, NTOK / 128), 256, GEMM_SMEM_BYTES>>>(
        xn, wqkvt, qkv, NTOK, TRIPLE, DIM, nullptr);

    // 3) Attention (tensor-core, cp.async pipelined)
    int att_smem = ATT_SMEM_FLOATS * (int)sizeof(float); // 106,496 B
    cudaFuncSetAttribute(attn_tc_kernel,
                         cudaFuncAttributeMaxDynamicSharedMemorySize, att_smem);
    attn_tc_kernel<<<dim3(TSEQ / 128, NH, NB), 256, att_smem>>>(qkv, ao);

    // 4) Output projection + bias: [8192,1024] @ [1024,1024] + b
    cudaFuncSetAttribute(gemm_tf32_pipe<true, false>,
                         cudaFuncAttributeMaxDynamicSharedMemorySize, GEMM_SMEM_BYTES);
    gemm_tf32_pipe<true, false><<<dim3(DIM / 128, NTOK / 128), 256, GEMM_SMEM_BYTES>>>(
        ao, woutt, out, NTOK, DIM, DIM, b_out);
}

// round 16
// speedup vs baseline: 1.2774x; 1.2761x over previous
#include <cuda_runtime.h>
#include <cuda_fp16.h>
#include <math.h>
#include <stdint.h>

#define NTOK 8192
#define DIM 1024
#define TRIPLE 3072
#define TSEQ 2048
#define NB 4
#define NH 16
#define DH 64
#define ATT_SCALE 0.125f

// Scratch (allocation-free: device globals)
__device__ __half g_xn[(size_t)NTOK * DIM];      // 16 MB (fp16)
__device__ float  g_qkv[(size_t)NTOK * TRIPLE];  // 96 MB (tf32-rounded fp32)
__device__ __half g_ao[(size_t)NTOK * DIM];      // 16 MB (fp16)
__device__ __half g_wqkv[(size_t)DIM * TRIPLE];  // transposed [3072,1024], fp16
__device__ __half g_wout[(size_t)DIM * DIM];     // transposed [1024,1024], fp16

// ---------------------------------------------------------------------------
// Helpers
// ---------------------------------------------------------------------------
__device__ __forceinline__ float f2tf32(float f) {
    uint32_t r;
    asm("cvt.rna.tf32.f32 %0, %1;" : "=r"(r) : "f"(f));
    return __uint_as_float(r);
}

__device__ __forceinline__ void mma_tf32(float c[4],
                                         uint32_t a0, uint32_t a1, uint32_t a2, uint32_t a3,
                                         uint32_t b0, uint32_t b1) {
    asm volatile(
        "mma.sync.aligned.m16n8k8.row.col.f32.tf32.tf32.f32 "
        "{%0,%1,%2,%3}, {%4,%5,%6,%7}, {%8,%9}, {%0,%1,%2,%3};"
        : "+f"(c[0]), "+f"(c[1]), "+f"(c[2]), "+f"(c[3])
        : "r"(a0), "r"(a1), "r"(a2), "r"(a3), "r"(b0), "r"(b1));
}

__device__ __forceinline__ void mma_f16(float c[4],
                                        uint32_t a0, uint32_t a1, uint32_t a2, uint32_t a3,
                                        uint32_t b0, uint32_t b1) {
    asm volatile(
        "mma.sync.aligned.m16n8k16.row.col.f32.f16.f16.f32 "
        "{%0,%1,%2,%3}, {%4,%5,%6,%7}, {%8,%9}, {%0,%1,%2,%3};"
        : "+f"(c[0]), "+f"(c[1]), "+f"(c[2]), "+f"(c[3])
        : "r"(a0), "r"(a1), "r"(a2), "r"(a3), "r"(b0), "r"(b1));
}

__device__ __forceinline__ void cp16(void* smem_dst, const void* gmem_src) {
    uint32_t s = (uint32_t)__cvta_generic_to_shared(smem_dst);
    asm volatile("cp.async.cg.shared.global [%0], [%1], 16;" :: "r"(s), "l"(gmem_src));
}
#define CP_COMMIT() asm volatile("cp.async.commit_group;" ::: "memory")
#define CP_WAIT0()  asm volatile("cp.async.wait_group 0;" ::: "memory")

// ---------------------------------------------------------------------------
// Transpose + fp16 round: out[c][r] = half(in[r][c]). in [R, C], out [C, R].
// ---------------------------------------------------------------------------
__global__ __launch_bounds__(256) void transpose_half_kernel(
    const float* __restrict__ in, __half* __restrict__ out, int R, int Ccols)
{
    __shared__ float tile[32][33];
    int tx = threadIdx.x & 31, ty = threadIdx.x >> 5;   // 32 x 8
    int x0 = blockIdx.x * 32, y0 = blockIdx.y * 32;
    #pragma unroll
    for (int i = 0; i < 32; i += 8)
        tile[ty + i][tx] = in[(size_t)(y0 + ty + i) * Ccols + x0 + tx];
    __syncthreads();
    #pragma unroll
    for (int i = 0; i < 32; i += 8)
        out[(size_t)(x0 + ty + i) * R + y0 + tx] = __float2half_rn(tile[tx][ty + i]);
}

// ---------------------------------------------------------------------------
// LayerNorm: one block per row of 1024, 256 threads x float4. Output fp16.
// ---------------------------------------------------------------------------
__global__ __launch_bounds__(256) void ln_kernel(
    const float* __restrict__ x,
    const float* __restrict__ gamma,
    const float* __restrict__ beta)
{
    int row = blockIdx.x;
    int t = threadIdx.x;
    const float4* xr = reinterpret_cast<const float4*>(x) + (size_t)row * (DIM / 4);
    float4 v = xr[t];

    __shared__ float red[8];

    float s = v.x + v.y + v.z + v.w;
    #pragma unroll
    for (int o = 16; o > 0; o >>= 1) s += __shfl_xor_sync(0xffffffffu, s, o);
    if ((t & 31) == 0) red[t >> 5] = s;
    __syncthreads();
    float mu = 0.f;
    #pragma unroll
    for (int i = 0; i < 8; i++) mu += red[i];
    mu *= (1.0f / DIM);
    __syncthreads();

    float dx = v.x - mu, dy = v.y - mu, dz = v.z - mu, dw = v.w - mu;
    float s2 = dx * dx + dy * dy + dz * dz + dw * dw;
    #pragma unroll
    for (int o = 16; o > 0; o >>= 1) s2 += __shfl_xor_sync(0xffffffffu, s2, o);
    if ((t & 31) == 0) red[t >> 5] = s2;
    __syncthreads();
    float var = 0.f;
    #pragma unroll
    for (int i = 0; i < 8; i++) var += red[i];
    var *= (1.0f / DIM);
    float r = rsqrtf(var + 1e-5f);

    float4 g = reinterpret_cast<const float4*>(gamma)[t];
    float4 bb = reinterpret_cast<const float4*>(beta)[t];
    float ox = dx * r * g.x + bb.x;
    float oy = dy * r * g.y + bb.y;
    float oz = dz * r * g.z + bb.z;
    float ow = dw * r * g.w + bb.w;
    __half2* outp = reinterpret_cast<__half2*>(g_xn) + (size_t)row * (DIM / 2);
    outp[t * 2 + 0] = __floats2half2_rn(ox, oy);
    outp[t * 2 + 1] = __floats2half2_rn(oz, ow);
}

// ---------------------------------------------------------------------------
// fp16 GEMM (m16n8k16, fp32 accumulate), cp.async double-buffered.
// C[M,N](fp32) = A[M,K](half) @ Bt[N,K](half)^T (+bias).
// CTA tile 128x128, BK=64, 256 threads = 8 warps (4m x 2n), warp tile 32x64.
// Smem: A/B stages 128 rows x 72 halves (stride pad): frag u32 LDS word
// index = grp*36+tg (mod 32 = grp*4+tg) -> conflict-free.
// Stages: A0|A1|B0|B1 @ 18,432 B = 73,728 B; x2 CTA = 147 KB OK.
// ---------------------------------------------------------------------------
#define HBK 64
#define HSTR 72                       // halves per smem row
#define HGS_BYTES (128 * HSTR * 2)    // 18,432 B per stage
#define HG_SMEM_BYTES (4 * HGS_BYTES)

template <bool HAS_BIAS, bool ROUND_OUT>
__global__ __launch_bounds__(256, 2) void gemm_f16_pipe(
    const __half* __restrict__ A,
    const __half* __restrict__ Bt,
    float* __restrict__ C,
    int M, int N, int K,
    const float* __restrict__ bias)
{
    extern __shared__ __align__(16) char smc[];
    __half* AsBase = (__half*)smc;                      // [2][128][72]
    __half* BsBase = (__half*)(smc + 2 * HGS_BYTES);    // [2][128][72]

    int t = threadIdx.x;
    int lane = t & 31;
    int warp = t >> 5;       // 0..7
    int warp_m = warp & 3;   // m offset *32
    int warp_n = warp >> 2;  // n offset *64
    int grp = lane >> 2;     // 0..7
    int tg = lane & 3;       // 0..3
    int mBase = blockIdx.y * 128;
    int nBase = blockIdx.x * 128;

    float acc[2][8][4];
    #pragma unroll
    for (int mi = 0; mi < 2; mi++)
        #pragma unroll
        for (int f = 0; f < 8; f++)
            #pragma unroll
            for (int j = 0; j < 4; j++) acc[mi][f][j] = 0.f;

    // Prefetch tile 0: 128 rows x 64 halves (128 B) per tensor = 1024 chunks
    {
        __half* As = AsBase;
        __half* Bs = BsBase;
        #pragma unroll
        for (int i = 0; i < 4; i++) {
            int fid = t + i * 256;
            int r = fid >> 3, c = fid & 7;
            cp16(&As[r * HSTR + c * 8], &A[(size_t)(mBase + r) * K + c * 8]);
            cp16(&Bs[r * HSTR + c * 8], &Bt[(size_t)(nBase + r) * K + c * 8]);
        }
        CP_COMMIT();
    }

    int T = K / HBK;
    for (int kt = 0; kt < T; kt++) {
        CP_WAIT0();
        __syncthreads();
        if (kt + 1 < T) {
            int k0 = (kt + 1) * HBK;
            int sn = (kt + 1) & 1;
            __half* As = AsBase + sn * (HGS_BYTES / 2);
            __half* Bs = BsBase + sn * (HGS_BYTES / 2);
            #pragma unroll
            for (int i = 0; i < 4; i++) {
                int fid = t + i * 256;
                int r = fid >> 3, c = fid & 7;
                cp16(&As[r * HSTR + c * 8], &A[(size_t)(mBase + r) * K + k0 + c * 8]);
                cp16(&Bs[r * HSTR + c * 8], &Bt[(size_t)(nBase + r) * K + k0 + c * 8]);
            }
            CP_COMMIT();
        }

        const __half* As = AsBase + (kt & 1) * (HGS_BYTES / 2);
        const __half* Bs = BsBase + (kt & 1) * (HGS_BYTES / 2);
        #pragma unroll
        for (int ks = 0; ks < 4; ks++) {
            int kk = ks * 16;
            uint32_t af[2][4];
            #pragma unroll
            for (int mi = 0; mi < 2; mi++) {
                int m = warp_m * 32 + mi * 16;
                const __half* r0 = &As[(m + grp) * HSTR + kk];
                const __half* r1 = &As[(m + grp + 8) * HSTR + kk];
                af[mi][0] = *reinterpret_cast<const uint32_t*>(r0 + 2 * tg);
                af[mi][1] = *reinterpret_cast<const uint32_t*>(r1 + 2 * tg);
                af[mi][2] = *reinterpret_cast<const uint32_t*>(r0 + 2 * tg + 8);
                af[mi][3] = *reinterpret_cast<const uint32_t*>(r1 + 2 * tg + 8);
            }
            #pragma unroll
            for (int f = 0; f < 8; f++) {
                int n = warp_n * 64 + f * 8 + grp;
                const __half* br = &Bs[n * HSTR + kk];
                uint32_t b0 = *reinterpret_cast<const uint32_t*>(br + 2 * tg);
                uint32_t b1 = *reinterpret_cast<const uint32_t*>(br + 2 * tg + 8);
                #pragma unroll
                for (int mi = 0; mi < 2; mi++)
                    mma_f16(acc[mi][f], af[mi][0], af[mi][1], af[mi][2], af[mi][3],
                            b0, b1);
            }
        }
        // No trailing barrier: stage (kt&1) is next written by copy kt+2, which
        // every thread issues only after passing the kt+1 top barrier.
    }

    // Epilogue (C fragment mapping identical to k8 layout)
    #pragma unroll
    for (int mi = 0; mi < 2; mi++) {
        int r0 = mBase + warp_m * 32 + mi * 16 + grp;
        #pragma unroll
        for (int f = 0; f < 8; f++) {
            int col = nBase + warp_n * 64 + f * 8 + 2 * tg;
            float2 c01 = make_float2(acc[mi][f][0], acc[mi][f][1]);
            float2 c23 = make_float2(acc[mi][f][2], acc[mi][f][3]);
            if (HAS_BIAS) {
                float b0v = bias[col], b1v = bias[col + 1];
                c01.x += b0v; c01.y += b1v;
                c23.x += b0v; c23.y += b1v;
            }
            if (ROUND_OUT) {
                c01.x = f2tf32(c01.x); c01.y = f2tf32(c01.y);
                c23.x = f2tf32(c23.x); c23.y = f2tf32(c23.y);
            }
            *reinterpret_cast<float2*>(&C[(size_t)r0 * N + col]) = c01;
            *reinterpret_cast<float2*>(&C[(size_t)(r0 + 8) * N + col]) = c23;
        }
    }
}

// ---------------------------------------------------------------------------
// Flash attention (measured-good tf32 path, unchanged except epilogue writes
// fp16 ao). qkv is tf32-rounded fp32. 256 thr, 8 warps x 16 q rows.
// ---------------------------------------------------------------------------
#define KS_STRIDE 68
#define VS_STRIDE 72
#define QP_STRIDE 68
#define AT_KS (64 * KS_STRIDE)
#define AT_VS (64 * VS_STRIDE)
#define ATT_SMEM_FLOATS (2 * AT_KS + 2 * AT_VS + 128 * QP_STRIDE)

__global__ __launch_bounds__(256, 2) void attn_tc_kernel(
    const float* __restrict__ qkv,
    __half* __restrict__ ao)
{
    extern __shared__ __align__(16) float sm[];
    float* KsBase = sm;
    float* VsBase = sm + 2 * AT_KS;
    float* QPs    = sm + 2 * AT_KS + 2 * AT_VS;

    int t = threadIdx.x;
    int lane = t & 31;
    int warp = t >> 5;
    int grp = lane >> 2;
    int tg = lane & 3;
    int wq = warp * 16;

    int qtile = blockIdx.x;
    int h = blockIdx.y;
    int b = blockIdx.z;

    size_t tokRowBase = (size_t)b * TSEQ;
    const float* Qg = qkv + tokRowBase * TRIPLE + h * DH;
    const float* Kg = qkv + tokRowBase * TRIPLE + DIM + h * DH;
    const float* Vg = qkv + tokRowBase * TRIPLE + 2 * DIM + h * DH;
    int qBase = qtile * 128;

    {
        float* Ks = KsBase;
        float* Vs = VsBase;
        #pragma unroll
        for (int i = 0; i < 4; i++) {
            int fid = t + i * 256;
            int r = fid >> 4, c = (fid & 15) << 2;
            cp16(&Ks[r * KS_STRIDE + c], &Kg[(size_t)r * TRIPLE + c]);
            cp16(&Vs[r * VS_STRIDE + c], &Vg[(size_t)r * TRIPLE + c]);
        }
        CP_COMMIT();
    }

    #pragma unroll
    for (int i = 0; i < 8; i++) {
        int fid = i * 32 + lane;
        int r = fid >> 4;
        int c = (fid & 15) << 2;
        float4 v = *reinterpret_cast<const float4*>(
            &Qg[(size_t)(qBase + wq + r) * TRIPLE + c]);
        v.x *= ATT_SCALE; v.y *= ATT_SCALE; v.z *= ATT_SCALE; v.w *= ATT_SCALE;
        *reinterpret_cast<float4*>(&QPs[(wq + r) * QP_STRIDE + c]) = v;
    }
    __syncwarp();

    uint32_t qa[8][4];
    #pragma unroll
    for (int ks = 0; ks < 8; ks++) {
        int k = ks * 8;
        qa[ks][0] = __float_as_uint(QPs[(wq + grp) * QP_STRIDE + k + tg]);
        qa[ks][1] = __float_as_uint(QPs[(wq + grp + 8) * QP_STRIDE + k + tg]);
        qa[ks][2] = __float_as_uint(QPs[(wq + grp) * QP_STRIDE + k + tg + 4]);
        qa[ks][3] = __float_as_uint(QPs[(wq + grp + 8) * QP_STRIDE + k + tg + 4]);
    }

    float o_acc[8][4];
    #pragma unroll
    for (int f = 0; f < 8; f++)
        #pragma unroll
        for (int j = 0; j < 4; j++) o_acc[f][j] = 0.f;
    float m0 = -INFINITY, m1 = -INFINITY, l0 = 0.f, l1 = 0.f;

    const int NT = TSEQ / 64;
    for (int kt = 0; kt < NT; kt++) {
        CP_WAIT0();
        __syncthreads();
        if (kt + 1 < NT) {
            int kBase = (kt + 1) * 64;
            int sn = (kt + 1) & 1;
            float* Ks = KsBase + sn * AT_KS;
            float* Vs = VsBase + sn * AT_VS;
            #pragma unroll
            for (int i = 0; i < 4; i++) {
                int fid = t + i * 256;
                int r = fid >> 4, c = (fid & 15) << 2;
                cp16(&Ks[r * KS_STRIDE + c], &Kg[(size_t)(kBase + r) * TRIPLE + c]);
                cp16(&Vs[r * VS_STRIDE + c], &Vg[(size_t)(kBase + r) * TRIPLE + c]);
            }
            CP_COMMIT();
        }
        const float* Ks = KsBase + (kt & 1) * AT_KS;
        const float* Vs = VsBase + (kt & 1) * AT_VS;

        float s[8][4];
        #pragma unroll
        for (int f = 0; f < 8; f++)
            #pragma unroll
            for (int j = 0; j < 4; j++) s[f][j] = 0.f;
        #pragma unroll
        for (int ks = 0; ks < 8; ks++) {
            int k = ks * 8;
            #pragma unroll
            for (int f = 0; f < 8; f++) {
                int key = f * 8 + grp;
                uint32_t b0 = __float_as_uint(Ks[key * KS_STRIDE + k + tg]);
                uint32_t b1 = __float_as_uint(Ks[key * KS_STRIDE + k + tg + 4]);
                mma_tf32(s[f], qa[ks][0], qa[ks][1], qa[ks][2], qa[ks][3], b0, b1);
            }
        }

        float rm0 = -INFINITY, rm1 = -INFINITY;
        #pragma unroll
        for (int f = 0; f < 8; f++) {
            rm0 = fmaxf(rm0, fmaxf(s[f][0], s[f][1]));
            rm1 = fmaxf(rm1, fmaxf(s[f][2], s[f][3]));
        }
        #pragma unroll
        for (int o = 1; o <= 2; o <<= 1) {
            rm0 = fmaxf(rm0, __shfl_xor_sync(0xffffffffu, rm0, o));
            rm1 = fmaxf(rm1, __shfl_xor_sync(0xffffffffu, rm1, o));
        }
        float mn0 = fmaxf(m0, rm0), mn1 = fmaxf(m1, rm1);
        float a0 = __expf(m0 - mn0), a1 = __expf(m1 - mn1);
        float rs0 = 0.f, rs1 = 0.f;
        #pragma unroll
        for (int f = 0; f < 8; f++) {
            s[f][0] = __expf(s[f][0] - mn0);
            s[f][1] = __expf(s[f][1] - mn0);
            s[f][2] = __expf(s[f][2] - mn1);
            s[f][3] = __expf(s[f][3] - mn1);
            rs0 += s[f][0] + s[f][1];
            rs1 += s[f][2] + s[f][3];
        }
        #pragma unroll
        for (int o = 1; o <= 2; o <<= 1) {
            rs0 += __shfl_xor_sync(0xffffffffu, rs0, o);
            rs1 += __shfl_xor_sync(0xffffffffu, rs1, o);
        }
        l0 = l0 * a0 + rs0;
        l1 = l1 * a1 + rs1;
        m0 = mn0; m1 = mn1;
        #pragma unroll
        for (int f = 0; f < 8; f++) {
            o_acc[f][0] *= a0; o_acc[f][1] *= a0;
            o_acc[f][2] *= a1; o_acc[f][3] *= a1;
        }

        #pragma unroll
        for (int f = 0; f < 8; f++) {
            int col = f * 8 + 2 * tg;
            float2 p01 = make_float2(f2tf32(s[f][0]), f2tf32(s[f][1]));
            float2 p23 = make_float2(f2tf32(s[f][2]), f2tf32(s[f][3]));
            *reinterpret_cast<float2*>(&QPs[(wq + grp) * QP_STRIDE + col]) = p01;
            *reinterpret_cast<float2*>(&QPs[(wq + grp + 8) * QP_STRIDE + col]) = p23;
        }
        __syncwarp();

        #pragma unroll
        for (int ks = 0; ks < 8; ks++) {
            int k = ks * 8;
            uint32_t pa0 = __float_as_uint(QPs[(wq + grp) * QP_STRIDE + k + tg]);
            uint32_t pa1 = __float_as_uint(QPs[(wq + grp + 8) * QP_STRIDE + k + tg]);
            uint32_t pa2 = __float_as_uint(QPs[(wq + grp) * QP_STRIDE + k + tg + 4]);
            uint32_t pa3 = __float_as_uint(QPs[(wq + grp + 8) * QP_STRIDE + k + tg + 4]);
            #pragma unroll
            for (int f = 0; f < 8; f++) {
                int n = f * 8 + grp;
                uint32_t b0 = __float_as_uint(Vs[(k + tg) * VS_STRIDE + n]);
                uint32_t b1 = __float_as_uint(Vs[(k + tg + 4) * VS_STRIDE + n]);
                mma_tf32(o_acc[f], pa0, pa1, pa2, pa3, b0, b1);
            }
        }
    }

    // Normalize + write fp16 ao (out-projection consumes half)
    float inv0 = 1.0f / l0, inv1 = 1.0f / l1;
    size_t gr0 = tokRowBase + qBase + wq + grp;
    size_t gr1 = gr0 + 8;
    #pragma unroll
    for (int f = 0; f < 8; f++) {
        int col = h * DH + f * 8 + 2 * tg;
        __half2 h01 = __floats2half2_rn(o_acc[f][0] * inv0, o_acc[f][1] * inv0);
        __half2 h23 = __floats2half2_rn(o_acc[f][2] * inv1, o_acc[f][3] * inv1);
        *reinterpret_cast<__half2*>(&ao[gr0 * DIM + col]) = h01;
        *reinterpret_cast<__half2*>(&ao[gr1 * DIM + col]) = h23;
    }
}

// ---------------------------------------------------------------------------
extern "C" void kernel_launch(void* const* d_in, const int* in_sizes, int n_in,
                              void* d_out, int out_size)
{
    const float* x      = (const float*)d_in[0];
    const float* gamma  = (const float*)d_in[1];
    const float* beta   = (const float*)d_in[2];
    const float* w_qkv  = (const float*)d_in[3];
    const float* w_out  = (const float*)d_in[4];
    const float* b_out  = (const float*)d_in[5];
    float* out = (float*)d_out;

    void* p;
    cudaGetSymbolAddress(&p, g_xn);   __half* xn    = (__half*)p;
    cudaGetSymbolAddress(&p, g_qkv);  float*  qkv   = (float*)p;
    cudaGetSymbolAddress(&p, g_ao);   __half* ao    = (__half*)p;
    cudaGetSymbolAddress(&p, g_wqkv); __half* wqkvT = (__half*)p;
    cudaGetSymbolAddress(&p, g_wout); __half* woutT = (__half*)p;

    // 0) Transpose + fp16-round weights: GEMM wants B as [N,K] K-major
    transpose_half_kernel<<<dim3(TRIPLE / 32, DIM / 32), 256>>>(w_qkv, wqkvT, DIM, TRIPLE);
    transpose_half_kernel<<<dim3(DIM / 32, DIM / 32), 256>>>(w_out, woutT, DIM, DIM);

    // 1) LayerNorm (writes fp16 xn)
    ln_kernel<<<NTOK, 256>>>(x, gamma, beta);

    // 2) QKV projection (fp16 mma): [8192,1024] @ [1024,3072] -> tf32-rounded qkv
    cudaFuncSetAttribute(gemm_f16_pipe<false, true>,
                         cudaFuncAttributeMaxDynamicSharedMemorySize, HG_SMEM_BYTES);
    gemm_f16_pipe<false, true><<<dim3(TRIPLE / 128, NTOK / 128), 256, HG_SMEM_BYTES>>>(
        xn, wqkvT, qkv, NTOK, TRIPLE, DIM, nullptr);

    // 3) Attention (tf32 mma path, measured-good; writes fp16 ao)
    int att_smem = ATT_SMEM_FLOATS * (int)sizeof(float);
    cudaFuncSetAttribute(attn_tc_kernel,
                         cudaFuncAttributeMaxDynamicSharedMemorySize, att_smem);
    attn_tc_kernel<<<dim3(TSEQ / 128, NH, NB), 256, att_smem>>>(qkv, ao);

    // 4) Output projection + bias (fp16 mma): [8192,1024] @ [1024,1024] + b
    cudaFuncSetAttribute(gemm_f16_pipe<true, false>,
                         cudaFuncAttributeMaxDynamicSharedMemorySize, HG_SMEM_BYTES);
    gemm_f16_pipe<true, false><<<dim3(DIM / 128, NTOK / 128), 256, HG_SMEM_BYTES>>>(
        ao, woutT, out, NTOK, DIM, DIM, b_out);
}

// round 17
// speedup vs baseline: 1.5903x; 1.2450x over previous
#include <cuda_runtime.h>
#include <cuda_fp16.h>
#include <math.h>
#include <stdint.h>

#define NTOK 8192
#define DIM 1024
#define TRIPLE 3072
#define TSEQ 2048
#define NB 4
#define NH 16
#define DH 64

// Scratch (allocation-free: device globals)
__device__ __half g_xn[(size_t)NTOK * DIM];      // 16 MB (fp16)
__device__ __half g_qkv[(size_t)NTOK * TRIPLE];  // 48 MB (fp16)
__device__ __half g_ao[(size_t)NTOK * DIM];      // 16 MB (fp16)
__device__ __half g_wqkv[(size_t)DIM * TRIPLE];  // transposed [3072,1024], fp16
__device__ __half g_wout[(size_t)DIM * DIM];     // transposed [1024,1024], fp16

// ---------------------------------------------------------------------------
// Helpers
// ---------------------------------------------------------------------------
__device__ __forceinline__ void mma_f16(float c[4],
                                        uint32_t a0, uint32_t a1, uint32_t a2, uint32_t a3,
                                        uint32_t b0, uint32_t b1) {
    asm volatile(
        "mma.sync.aligned.m16n8k16.row.col.f32.f16.f16.f32 "
        "{%0,%1,%2,%3}, {%4,%5,%6,%7}, {%8,%9}, {%0,%1,%2,%3};"
        : "+f"(c[0]), "+f"(c[1]), "+f"(c[2]), "+f"(c[3])
        : "r"(a0), "r"(a1), "r"(a2), "r"(a3), "r"(b0), "r"(b1));
}

__device__ __forceinline__ void cp16(void* smem_dst, const void* gmem_src) {
    uint32_t s = (uint32_t)__cvta_generic_to_shared(smem_dst);
    asm volatile("cp.async.cg.shared.global [%0], [%1], 16;" :: "r"(s), "l"(gmem_src));
}
#define CP_COMMIT() asm volatile("cp.async.commit_group;" ::: "memory")
#define CP_WAIT0()  asm volatile("cp.async.wait_group 0;" ::: "memory")

__device__ __forceinline__ uint32_t pack_h2(__half lo, __half hi) {
    __half2 h = __halves2half2(lo, hi);
    return *reinterpret_cast<uint32_t*>(&h);
}

// ---------------------------------------------------------------------------
// Transpose + fp16 round: out[c][r] = half(in[r][c]). in [R, C], out [C, R].
// ---------------------------------------------------------------------------
__global__ __launch_bounds__(256) void transpose_half_kernel(
    const float* __restrict__ in, __half* __restrict__ out, int R, int Ccols)
{
    __shared__ float tile[32][33];
    int tx = threadIdx.x & 31, ty = threadIdx.x >> 5;   // 32 x 8
    int x0 = blockIdx.x * 32, y0 = blockIdx.y * 32;
    #pragma unroll
    for (int i = 0; i < 32; i += 8)
        tile[ty + i][tx] = in[(size_t)(y0 + ty + i) * Ccols + x0 + tx];
    __syncthreads();
    #pragma unroll
    for (int i = 0; i < 32; i += 8)
        out[(size_t)(x0 + ty + i) * R + y0 + tx] = __float2half_rn(tile[tx][ty + i]);
}

// ---------------------------------------------------------------------------
// LayerNorm: one block per row of 1024, 256 threads x float4. Output fp16.
// ---------------------------------------------------------------------------
__global__ __launch_bounds__(256) void ln_kernel(
    const float* __restrict__ x,
    const float* __restrict__ gamma,
    const float* __restrict__ beta)
{
    int row = blockIdx.x;
    int t = threadIdx.x;
    const float4* xr = reinterpret_cast<const float4*>(x) + (size_t)row * (DIM / 4);
    float4 v = xr[t];

    __shared__ float red[8];

    float s = v.x + v.y + v.z + v.w;
    #pragma unroll
    for (int o = 16; o > 0; o >>= 1) s += __shfl_xor_sync(0xffffffffu, s, o);
    if ((t & 31) == 0) red[t >> 5] = s;
    __syncthreads();
    float mu = 0.f;
    #pragma unroll
    for (int i = 0; i < 8; i++) mu += red[i];
    mu *= (1.0f / DIM);
    __syncthreads();

    float dx = v.x - mu, dy = v.y - mu, dz = v.z - mu, dw = v.w - mu;
    float s2 = dx * dx + dy * dy + dz * dz + dw * dw;
    #pragma unroll
    for (int o = 16; o > 0; o >>= 1) s2 += __shfl_xor_sync(0xffffffffu, s2, o);
    if ((t & 31) == 0) red[t >> 5] = s2;
    __syncthreads();
    float var = 0.f;
    #pragma unroll
    for (int i = 0; i < 8; i++) var += red[i];
    var *= (1.0f / DIM);
    float r = rsqrtf(var + 1e-5f);

    float4 g = reinterpret_cast<const float4*>(gamma)[t];
    float4 bb = reinterpret_cast<const float4*>(beta)[t];
    float ox = dx * r * g.x + bb.x;
    float oy = dy * r * g.y + bb.y;
    float oz = dz * r * g.z + bb.z;
    float ow = dw * r * g.w + bb.w;
    __half2* outp = reinterpret_cast<__half2*>(g_xn) + (size_t)row * (DIM / 2);
    outp[t * 2 + 0] = __floats2half2_rn(ox, oy);
    outp[t * 2 + 1] = __floats2half2_rn(oz, ow);
}

// ---------------------------------------------------------------------------
// fp16 GEMM (m16n8k16, fp32 accumulate), cp.async double-buffered.
// C[M,N] = A[M,K](half) @ Bt[N,K](half)^T (+bias). OUT_HALF: C is half.
// CTA tile 128x128, BK=64, 256 threads = 8 warps (4m x 2n), warp tile 32x64.
// ---------------------------------------------------------------------------
#define HBK 64
#define HSTR 72                       // halves per smem row
#define HGS_BYTES (128 * HSTR * 2)    // 18,432 B per stage
#define HG_SMEM_BYTES (4 * HGS_BYTES)

template <bool HAS_BIAS, bool OUT_HALF>
__global__ __launch_bounds__(256, 2) void gemm_f16_pipe(
    const __half* __restrict__ A,
    const __half* __restrict__ Bt,
    void* __restrict__ Cv,
    int M, int N, int K,
    const float* __restrict__ bias)
{
    extern __shared__ __align__(16) char smc[];
    __half* AsBase = (__half*)smc;                      // [2][128][72]
    __half* BsBase = (__half*)(smc + 2 * HGS_BYTES);    // [2][128][72]

    int t = threadIdx.x;
    int lane = t & 31;
    int warp = t >> 5;       // 0..7
    int warp_m = warp & 3;   // m offset *32
    int warp_n = warp >> 2;  // n offset *64
    int grp = lane >> 2;     // 0..7
    int tg = lane & 3;       // 0..3
    int mBase = blockIdx.y * 128;
    int nBase = blockIdx.x * 128;

    float acc[2][8][4];
    #pragma unroll
    for (int mi = 0; mi < 2; mi++)
        #pragma unroll
        for (int f = 0; f < 8; f++)
            #pragma unroll
            for (int j = 0; j < 4; j++) acc[mi][f][j] = 0.f;

    {
        __half* As = AsBase;
        __half* Bs = BsBase;
        #pragma unroll
        for (int i = 0; i < 4; i++) {
            int fid = t + i * 256;
            int r = fid >> 3, c = fid & 7;
            cp16(&As[r * HSTR + c * 8], &A[(size_t)(mBase + r) * K + c * 8]);
            cp16(&Bs[r * HSTR + c * 8], &Bt[(size_t)(nBase + r) * K + c * 8]);
        }
        CP_COMMIT();
    }

    int T = K / HBK;
    for (int kt = 0; kt < T; kt++) {
        CP_WAIT0();
        __syncthreads();
        if (kt + 1 < T) {
            int k0 = (kt + 1) * HBK;
            int sn = (kt + 1) & 1;
            __half* As = AsBase + sn * (HGS_BYTES / 2);
            __half* Bs = BsBase + sn * (HGS_BYTES / 2);
            #pragma unroll
            for (int i = 0; i < 4; i++) {
                int fid = t + i * 256;
                int r = fid >> 3, c = fid & 7;
                cp16(&As[r * HSTR + c * 8], &A[(size_t)(mBase + r) * K + k0 + c * 8]);
                cp16(&Bs[r * HSTR + c * 8], &Bt[(size_t)(nBase + r) * K + k0 + c * 8]);
            }
            CP_COMMIT();
        }

        const __half* As = AsBase + (kt & 1) * (HGS_BYTES / 2);
        const __half* Bs = BsBase + (kt & 1) * (HGS_BYTES / 2);
        #pragma unroll
        for (int ks = 0; ks < 4; ks++) {
            int kk = ks * 16;
            uint32_t af[2][4];
            #pragma unroll
            for (int mi = 0; mi < 2; mi++) {
                int m = warp_m * 32 + mi * 16;
                const __half* r0 = &As[(m + grp) * HSTR + kk];
                const __half* r1 = &As[(m + grp + 8) * HSTR + kk];
                af[mi][0] = *reinterpret_cast<const uint32_t*>(r0 + 2 * tg);
                af[mi][1] = *reinterpret_cast<const uint32_t*>(r1 + 2 * tg);
                af[mi][2] = *reinterpret_cast<const uint32_t*>(r0 + 2 * tg + 8);
                af[mi][3] = *reinterpret_cast<const uint32_t*>(r1 + 2 * tg + 8);
            }
            #pragma unroll
            for (int f = 0; f < 8; f++) {
                int n = warp_n * 64 + f * 8 + grp;
                const __half* br = &Bs[n * HSTR + kk];
                uint32_t b0 = *reinterpret_cast<const uint32_t*>(br + 2 * tg);
                uint32_t b1 = *reinterpret_cast<const uint32_t*>(br + 2 * tg + 8);
                #pragma unroll
                for (int mi = 0; mi < 2; mi++)
                    mma_f16(acc[mi][f], af[mi][0], af[mi][1], af[mi][2], af[mi][3],
                            b0, b1);
            }
        }
    }

    #pragma unroll
    for (int mi = 0; mi < 2; mi++) {
        int r0 = mBase + warp_m * 32 + mi * 16 + grp;
        #pragma unroll
        for (int f = 0; f < 8; f++) {
            int col = nBase + warp_n * 64 + f * 8 + 2 * tg;
            float2 c01 = make_float2(acc[mi][f][0], acc[mi][f][1]);
            float2 c23 = make_float2(acc[mi][f][2], acc[mi][f][3]);
            if (HAS_BIAS) {
                float b0v = bias[col], b1v = bias[col + 1];
                c01.x += b0v; c01.y += b1v;
                c23.x += b0v; c23.y += b1v;
            }
            if (OUT_HALF) {
                __half* Ch = (__half*)Cv;
                *reinterpret_cast<__half2*>(&Ch[(size_t)r0 * N + col]) =
                    __floats2half2_rn(c01.x, c01.y);
                *reinterpret_cast<__half2*>(&Ch[(size_t)(r0 + 8) * N + col]) =
                    __floats2half2_rn(c23.x, c23.y);
            } else {
                float* Cf = (float*)Cv;
                *reinterpret_cast<float2*>(&Cf[(size_t)r0 * N + col]) = c01;
                *reinterpret_cast<float2*>(&Cf[(size_t)(r0 + 8) * N + col]) = c23;
            }
        }
    }
}

// ---------------------------------------------------------------------------
// Flash attention, fp16 m16n8k16 mma, fp32 online softmax, cp.async K/V
// double buffering. Block = (128-query tile, head, batch); 8 warps x 16 q rows.
// qkv is fp16. Q scale 0.125 exact in fp16. P stored fp16.
// Smem (halves): Ks[2][64][72], Vs[2][64][72], QPs[128][72] = 55,296 B.
// ---------------------------------------------------------------------------
#define KH_STR 72
#define AT_KH (64 * KH_STR)
#define ATT_SMEM_BYTES ((4 * AT_KH + 128 * KH_STR) * 2)

__global__ __launch_bounds__(256, 2) void attn_f16_kernel(
    const __half* __restrict__ qkv,
    __half* __restrict__ ao)
{
    extern __shared__ __align__(16) __half smh[];
    __half* KsBase = smh;                      // [2][64][72]
    __half* VsBase = smh + 2 * AT_KH;          // [2][64][72]
    __half* QPs    = smh + 4 * AT_KH;          // [128][72]

    int t = threadIdx.x;
    int lane = t & 31;
    int warp = t >> 5;     // 0..7
    int grp = lane >> 2;   // 0..7
    int tg = lane & 3;     // 0..3
    int wq = warp * 16;

    int qtile = blockIdx.x;
    int h = blockIdx.y;
    int b = blockIdx.z;

    size_t tokRowBase = (size_t)b * TSEQ;
    const __half* Qg = qkv + tokRowBase * TRIPLE + h * DH;
    const __half* Kg = qkv + tokRowBase * TRIPLE + DIM + h * DH;
    const __half* Vg = qkv + tokRowBase * TRIPLE + 2 * DIM + h * DH;
    int qBase = qtile * 128;

    // Prefetch K/V tile 0 (64 rows x 8 16B-chunks each; 256 thr -> 2 per tensor)
    {
        __half* Ks = KsBase;
        __half* Vs = VsBase;
        #pragma unroll
        for (int i = 0; i < 2; i++) {
            int fid = t + i * 256;
            int r = fid >> 3, c = fid & 7;
            cp16(&Ks[r * KH_STR + c * 8], &Kg[(size_t)r * TRIPLE + c * 8]);
            cp16(&Vs[r * KH_STR + c * 8], &Vg[(size_t)r * TRIPLE + c * 8]);
        }
        CP_COMMIT();
    }

    // Stage this warp's 16 Q rows (x0.125 exact), fp16
    {
        const __half2 sc = __half2half2(__float2half_rn(0.125f));
        #pragma unroll
        for (int i = 0; i < 4; i++) {
            int fid = i * 32 + lane;
            int r = fid >> 3, c = fid & 7;
            uint4 v = *reinterpret_cast<const uint4*>(
                &Qg[(size_t)(qBase + wq + r) * TRIPLE + c * 8]);
            __half2* hp = reinterpret_cast<__half2*>(&v);
            hp[0] = __hmul2(hp[0], sc);
            hp[1] = __hmul2(hp[1], sc);
            hp[2] = __hmul2(hp[2], sc);
            hp[3] = __hmul2(hp[3], sc);
            *reinterpret_cast<uint4*>(&QPs[(wq + r) * KH_STR + c * 8]) = v;
        }
    }
    __syncwarp();

    uint32_t qa[4][4];   // 4 k-steps over d=64
    #pragma unroll
    for (int ks = 0; ks < 4; ks++) {
        int kk = ks * 16;
        const __half* r0 = &QPs[(wq + grp) * KH_STR + kk];
        const __half* r1 = &QPs[(wq + grp + 8) * KH_STR + kk];
        qa[ks][0] = *reinterpret_cast<const uint32_t*>(r0 + 2 * tg);
        qa[ks][1] = *reinterpret_cast<const uint32_t*>(r1 + 2 * tg);
        qa[ks][2] = *reinterpret_cast<const uint32_t*>(r0 + 2 * tg + 8);
        qa[ks][3] = *reinterpret_cast<const uint32_t*>(r1 + 2 * tg + 8);
    }

    float o_acc[8][4];
    #pragma unroll
    for (int f = 0; f < 8; f++)
        #pragma unroll
        for (int j = 0; j < 4; j++) o_acc[f][j] = 0.f;
    float m0 = -INFINITY, m1 = -INFINITY, l0 = 0.f, l1 = 0.f;

    const int NT = TSEQ / 64;
    for (int kt = 0; kt < NT; kt++) {
        CP_WAIT0();
        __syncthreads();
        if (kt + 1 < NT) {
            int kBase = (kt + 1) * 64;
            int sn = (kt + 1) & 1;
            __half* Ks = KsBase + sn * AT_KH;
            __half* Vs = VsBase + sn * AT_KH;
            #pragma unroll
            for (int i = 0; i < 2; i++) {
                int fid = t + i * 256;
                int r = fid >> 3, c = fid & 7;
                cp16(&Ks[r * KH_STR + c * 8], &Kg[(size_t)(kBase + r) * TRIPLE + c * 8]);
                cp16(&Vs[r * KH_STR + c * 8], &Vg[(size_t)(kBase + r) * TRIPLE + c * 8]);
            }
            CP_COMMIT();
        }
        const __half* Ks = KsBase + (kt & 1) * AT_KH;
        const __half* Vs = VsBase + (kt & 1) * AT_KH;

        // S = Q K^T : warp computes 16 x 64 (4 k-steps x 8 key-groups)
        float s[8][4];
        #pragma unroll
        for (int f = 0; f < 8; f++)
            #pragma unroll
            for (int j = 0; j < 4; j++) s[f][j] = 0.f;
        #pragma unroll
        for (int ks = 0; ks < 4; ks++) {
            int kk = ks * 16;
            #pragma unroll
            for (int f = 0; f < 8; f++) {
                int key = f * 8 + grp;
                const __half* br = &Ks[key * KH_STR + kk];
                uint32_t b0 = *reinterpret_cast<const uint32_t*>(br + 2 * tg);
                uint32_t b1 = *reinterpret_cast<const uint32_t*>(br + 2 * tg + 8);
                mma_f16(s[f], qa[ks][0], qa[ks][1], qa[ks][2], qa[ks][3], b0, b1);
            }
        }

        // Online softmax (fp32)
        float rm0 = -INFINITY, rm1 = -INFINITY;
        #pragma unroll
        for (int f = 0; f < 8; f++) {
            rm0 = fmaxf(rm0, fmaxf(s[f][0], s[f][1]));
            rm1 = fmaxf(rm1, fmaxf(s[f][2], s[f][3]));
        }
        #pragma unroll
        for (int o = 1; o <= 2; o <<= 1) {
            rm0 = fmaxf(rm0, __shfl_xor_sync(0xffffffffu, rm0, o));
            rm1 = fmaxf(rm1, __shfl_xor_sync(0xffffffffu, rm1, o));
        }
        float mn0 = fmaxf(m0, rm0), mn1 = fmaxf(m1, rm1);
        float a0 = __expf(m0 - mn0), a1 = __expf(m1 - mn1);
        float rs0 = 0.f, rs1 = 0.f;
        #pragma unroll
        for (int f = 0; f < 8; f++) {
            s[f][0] = __expf(s[f][0] - mn0);
            s[f][1] = __expf(s[f][1] - mn0);
            s[f][2] = __expf(s[f][2] - mn1);
            s[f][3] = __expf(s[f][3] - mn1);
            rs0 += s[f][0] + s[f][1];
            rs1 += s[f][2] + s[f][3];
        }
        #pragma unroll
        for (int o = 1; o <= 2; o <<= 1) {
            rs0 += __shfl_xor_sync(0xffffffffu, rs0, o);
            rs1 += __shfl_xor_sync(0xffffffffu, rs1, o);
        }
        l0 = l0 * a0 + rs0;
        l1 = l1 * a1 + rs1;
        m0 = mn0; m1 = mn1;
        #pragma unroll
        for (int f = 0; f < 8; f++) {
            o_acc[f][0] *= a0; o_acc[f][1] *= a0;
            o_acc[f][2] *= a1; o_acc[f][3] *= a1;
        }

        // Write P (fp16) into this warp's own QPs rows: [q][key]
        #pragma unroll
        for (int f = 0; f < 8; f++) {
            int col = f * 8 + 2 * tg;
            *reinterpret_cast<__half2*>(&QPs[(wq + grp) * KH_STR + col]) =
                __floats2half2_rn(s[f][0], s[f][1]);
            *reinterpret_cast<__half2*>(&QPs[(wq + grp + 8) * KH_STR + col]) =
                __floats2half2_rn(s[f][2], s[f][3]);
        }
        __syncwarp();

        // O += P @ V : 4 k-steps over 64 keys, 8 d-groups
        #pragma unroll
        for (int ks = 0; ks < 4; ks++) {
            int kk = ks * 16;
            const __half* p0 = &QPs[(wq + grp) * KH_STR + kk];
            const __half* p1 = &QPs[(wq + grp + 8) * KH_STR + kk];
            uint32_t pa0 = *reinterpret_cast<const uint32_t*>(p0 + 2 * tg);
            uint32_t pa1 = *reinterpret_cast<const uint32_t*>(p1 + 2 * tg);
            uint32_t pa2 = *reinterpret_cast<const uint32_t*>(p0 + 2 * tg + 8);
            uint32_t pa3 = *reinterpret_cast<const uint32_t*>(p1 + 2 * tg + 8);
            #pragma unroll
            for (int f = 0; f < 8; f++) {
                int n = f * 8 + grp;
                uint32_t b0 = pack_h2(Vs[(kk + 2 * tg) * KH_STR + n],
                                      Vs[(kk + 2 * tg + 1) * KH_STR + n]);
                uint32_t b1 = pack_h2(Vs[(kk + 2 * tg + 8) * KH_STR + n],
                                      Vs[(kk + 2 * tg + 9) * KH_STR + n]);
                mma_f16(o_acc[f], pa0, pa1, pa2, pa3, b0, b1);
            }
        }
    }

    // Normalize + write fp16 ao
    float inv0 = 1.0f / l0, inv1 = 1.0f / l1;
    size_t gr0 = tokRowBase + qBase + wq + grp;
    size_t gr1 = gr0 + 8;
    #pragma unroll
    for (int f = 0; f < 8; f++) {
        int col = h * DH + f * 8 + 2 * tg;
        *reinterpret_cast<__half2*>(&ao[gr0 * DIM + col]) =
            __floats2half2_rn(o_acc[f][0] * inv0, o_acc[f][1] * inv0);
        *reinterpret_cast<__half2*>(&ao[gr1 * DIM + col]) =
            __floats2half2_rn(o_acc[f][2] * inv1, o_acc[f][3] * inv1);
    }
}

// ---------------------------------------------------------------------------
extern "C" void kernel_launch(void* const* d_in, const int* in_sizes, int n_in,
                              void* d_out, int out_size)
{
    const float* x      = (const float*)d_in[0];
    const float* gamma  = (const float*)d_in[1];
    const float* beta   = (const float*)d_in[2];
    const float* w_qkv  = (const float*)d_in[3];
    const float* w_out  = (const float*)d_in[4];
    const float* b_out  = (const float*)d_in[5];
    float* out = (float*)d_out;

    void* p;
    cudaGetSymbolAddress(&p, g_xn);   __half* xn    = (__half*)p;
    cudaGetSymbolAddress(&p, g_qkv);  __half* qkv   = (__half*)p;
    cudaGetSymbolAddress(&p, g_ao);   __half* ao    = (__half*)p;
    cudaGetSymbolAddress(&p, g_wqkv); __half* wqkvT = (__half*)p;
    cudaGetSymbolAddress(&p, g_wout); __half* woutT = (__half*)p;

    // 0) Transpose + fp16-round weights
    transpose_half_kernel<<<dim3(TRIPLE / 32, DIM / 32), 256>>>(w_qkv, wqkvT, DIM, TRIPLE);
    transpose_half_kernel<<<dim3(DIM / 32, DIM / 32), 256>>>(w_out, woutT, DIM, DIM);

    // 1) LayerNorm (writes fp16 xn)
    ln_kernel<<<NTOK, 256>>>(x, gamma, beta);

    // 2) QKV projection (fp16 mma) -> fp16 qkv
    cudaFuncSetAttribute(gemm_f16_pipe<false, true>,
                         cudaFuncAttributeMaxDynamicSharedMemorySize, HG_SMEM_BYTES);
    gemm_f16_pipe<false, true><<<dim3(TRIPLE / 128, NTOK / 128), 256, HG_SMEM_BYTES>>>(
        xn, wqkvT, qkv, NTOK, TRIPLE, DIM, nullptr);

    // 3) Attention (fp16 mma; writes fp16 ao)
    cudaFuncSetAttribute(attn_f16_kernel,
                         cudaFuncAttributeMaxDynamicSharedMemorySize, ATT_SMEM_BYTES);
    attn_f16_kernel<<<dim3(TSEQ / 128, NH, NB), 256, ATT_SMEM_BYTES>>>(qkv, ao);

    // 4) Output projection + bias (fp16 mma) -> fp32 out
    cudaFuncSetAttribute(gemm_f16_pipe<true, false>,
                         cudaFuncAttributeMaxDynamicSharedMemorySize, HG_SMEM_BYTES);
    gemm_f16_pipe<true, false><<<dim3(DIM / 128, NTOK / 128), 256, HG_SMEM_BYTES>>>(
        ao, woutT, out, NTOK, DIM, DIM, b_out);
}